// round 12
// baseline (speedup 1.0000x reference)
#include <cuda_runtime.h>
#include <cstdint>

// Problem constants
#define E_LEN  512
#define NFEA   8
#define NCLS   14
#define BATCH  8192
#define ROW    (E_LEN * NFEA)        // 4096 floats per sample
#define NPAIR  (NCLS * NCLS)         // 196

#define GRID   152                   // GB300: 152 SMs, 1 CTA each
#define TPB    512                   // 16 warps, 4/SMSP
#define WPB    (TPB / 32)
#define NWARPS (GRID * WPB)          // 2432
#define WSTR   10                    // u64 stride per e-row of packed w (80 B, 16B-aligned)

typedef unsigned long long u64;

__device__ float    g_block[GRID];
__device__ unsigned g_count = 0;

// ---- f32x2 helpers (ptxas never auto-emits FFMA2 from C++) ----
__device__ __forceinline__ u64 pk2(float lo, float hi) {
    u64 r; asm("mov.b64 %0, {%1, %2};" : "=l"(r) : "f"(lo), "f"(hi)); return r;
}
__device__ __forceinline__ void up2(float& lo, float& hi, u64 v) {
    asm("mov.b64 {%0, %1}, %2;" : "=f"(lo), "=f"(hi) : "l"(v));
}
__device__ __forceinline__ u64 bc2(float v) {
    u64 r; asm("mov.b64 %0, {%1, %1};" : "=l"(r) : "f"(v)); return r;
}
__device__ __forceinline__ u64 fma2(u64 a, u64 b, u64 c) {
    u64 d; asm("fma.rn.f32x2 %0, %1, %2, %3;" : "=l"(d) : "l"(a), "l"(b), "l"(c)); return d;
}
__device__ __forceinline__ u64 add2(u64 a, u64 b) {
    u64 d; asm("add.rn.f32x2 %0, %1, %2;" : "=l"(d) : "l"(a), "l"(b)); return d;
}

__device__ __forceinline__ float softplus_f(float v) {
    return fmaxf(v, 0.f) + log1pf(__expf(-fabsf(v)));
}

// Partitioned halving reduction among lanes of equal parity (masks 16,8,4,2).
template<int H, int W>
__device__ __forceinline__ void red_stage(u64* v, int lane) {
    const bool up = (lane & W) != 0;
    #pragma unroll
    for (int i = 0; i < H; i++) {
        u64 send = up ? v[i] : v[i + H];
        u64 recv = __shfl_xor_sync(0xffffffffu, send, W);
        u64 keep = up ? v[i + H] : v[i];
        v[i] = add2(keep, recv);
    }
}

// ---------- Single fused kernel: gram prologue + loss + grid reduction ----------
__global__ __launch_bounds__(TPB, 1)
void main_kernel(const float* __restrict__ x, const int* __restrict__ y,
                 const float* __restrict__ w, float* __restrict__ out) {
    // w packed e-major: u64 p (classes 2p,2p+1) at s_w[e*WSTR + p], p<7.
    // 80B e-stride -> LDS.128-friendly (16B aligned) and conflict-free mod-128.
    __shared__ u64   s_w[E_LEN * WSTR];        // 40 KB
    __shared__ u64   s_red[WPB][64];           // 8 KB
    __shared__ float s_dot[WPB][NCLS];
    __shared__ float s_G[NPAIR];
    __shared__ float s_wsum[WPB];
    __shared__ int   s_last;

    const int tid = threadIdx.x;
    const int lane = tid & 31, wid = tid >> 5;

    for (int idx = tid; idx < 7 * E_LEN; idx += TPB) {
        int e = idx & (E_LEN - 1);
        int p = idx >> 9;
        float2 wv = *(const float2*)(w + e * NCLS + 2 * p);   // even class -> 8B aligned
        s_w[e * WSTR + p] = pk2(wv.x, wv.y);
    }
    __syncthreads();

    // --- Gram prologue: 105 unique pairs, warp-per-pair ---
    {
        const float* wf = (const float*)s_w;   // w[e][c] at wf[e*2*WSTR + c]
        for (int p = wid; p < 105; p += WPB) {
            int c1 = 0, rem = p;
            while (rem >= NCLS - c1) { rem -= NCLS - c1; c1++; }
            int c2 = c1 + rem;
            float s = 0.f;
            #pragma unroll
            for (int k = 0; k < 16; k++) {
                int eb = (lane + 32 * k) * 2 * WSTR;
                s = fmaf(wf[eb + c1], wf[eb + c2], s);
            }
            #pragma unroll
            for (int o = 16; o; o >>= 1) s += __shfl_xor_sync(~0u, s, o);
            if (lane == 0) { s_G[c1 * NCLS + c2] = s; s_G[c2 * NCLS + c1] = s; }
        }
    }
    __syncthreads();

    // --- Main loop: warp per sample; lane pairs share e, split m 0-3 / 4-7 ---
    const int gw = wid * GRID + blockIdx.x;
    float wacc = 0.f;

    for (int s = gw; s < BATCH; s += NWARPS) {
        const float4* px = (const float4*)(x + (size_t)s * ROW);

        // depth-3 software pipeline; lane l reads float4 index 32*j + l (coalesced)
        float4 c0 = __ldcs(px + lane);
        float4 c1 = __ldcs(px + 32 + lane);
        float4 c2 = __ldcs(px + 64 + lane);

        u64 v[32];                              // f = m_local*8 + cc (cc<7; 7 pad)
        #pragma unroll
        for (int f = 0; f < 32; f++) v[f] = 0ull;
        float l1 = 0.f;

        #pragma unroll
        for (int j = 0; j < 32; j++) {
            int jn = (j + 3 < 32) ? (j + 3) : 31;
            float4 c3 = __ldcs(px + 32 * jn + lane);
            const int e = 16 * j + (lane >> 1);

            const u64* wp = s_w + e * WSTR;
            ulonglong2 wA = *(const ulonglong2*)(wp);       // cc0, cc1
            ulonglong2 wB = *(const ulonglong2*)(wp + 2);   // cc2, cc3
            ulonglong2 wC = *(const ulonglong2*)(wp + 4);   // cc4, cc5
            u64 w6 = wp[6];                                 // cc6
            u64 ww[7] = { wA.x, wA.y, wB.x, wB.y, wC.x, wC.y, w6 };

            u64 b0v = bc2(c0.x), b1v = bc2(c0.y), b2v = bc2(c0.z), b3v = bc2(c0.w);
            #pragma unroll
            for (int cc = 0; cc < 7; cc++) {
                v[0 * 8 + cc] = fma2(b0v, ww[cc], v[0 * 8 + cc]);
                v[1 * 8 + cc] = fma2(b1v, ww[cc], v[1 * 8 + cc]);
                v[2 * 8 + cc] = fma2(b2v, ww[cc], v[2 * 8 + cc]);
                v[3 * 8 + cc] = fma2(b3v, ww[cc], v[3 * 8 + cc]);
            }

            // per-(b,e) unbiased variance over 8 m: combine the two parity partials
            float p1 = (c0.x + c0.y) + (c0.z + c0.w);
            float p2 = fmaf(c0.x, c0.x, fmaf(c0.y, c0.y, fmaf(c0.z, c0.z, c0.w * c0.w)));
            u64 other = __shfl_xor_sync(~0u, pk2(p1, p2), 1);
            float q1, q2; up2(q1, q2, other);
            float s1 = p1 + q1, s2 = p2 + q2;
            float var = (s2 - s1 * s1 * 0.125f) * (1.0f / 7.0f);
            l1 += fabsf(var);                   // both parity lanes count -> x0.5 later

            c0 = c1; c1 = c2; c2 = c3;
        }

        // reduce 32 packed partials among same-parity lanes
        red_stage<16, 16>(v, lane);
        red_stage< 8,  8>(v, lane);
        red_stage< 4,  4>(v, lane);
        red_stage< 2,  2>(v, lane);
        s_red[wid][(lane & 1) * 32 + 2 * (lane >> 1)]     = v[0];
        s_red[wid][(lane & 1) * 32 + 2 * (lane >> 1) + 1] = v[1];
        __syncwarp();

        // dot[c] = max over m (m = 4*parity + m_local)
        if (lane < NCLS) {
            const float* rp = (const float*)&s_red[wid][0];
            int cc = lane >> 1, par = lane & 1;
            float mx = -3.4e38f;
            #pragma unroll
            for (int m = 0; m < 8; m++) {
                int h = m >> 2, ml = m & 3;
                mx = fmaxf(mx, rp[h * 64 + (ml * 8 + cc) * 2 + par]);
            }
            s_dot[wid][lane] = mx;
        }
        int yv = (lane < NCLS) ? __ldg(y + (size_t)s * NCLS + lane) : 0;
        unsigned mask = __ballot_sync(~0u, yv == 1);
        __syncwarp();

        // pairwise softplus + Gram sums, distributed over lanes
        float psum = 0.f, gs = 0.f, ds = 0.f;
        for (int idx = lane; idx < NPAIR; idx += 32) {
            int p = idx / NCLS, n = idx - p * NCLS;
            bool pp = (mask >> p) & 1, pn = (mask >> n) & 1;
            if (pp && !pn) psum += softplus_f(s_dot[wid][n] - s_dot[wid][p]);
            if (pp && pn) { float g = s_G[idx]; gs += g; if (p == n) ds += g; }
        }
        float li = l1;
        #pragma unroll
        for (int o = 16; o; o >>= 1) {
            psum += __shfl_xor_sync(~0u, psum, o);
            gs   += __shfl_xor_sync(~0u, gs,   o);
            ds   += __shfl_xor_sync(~0u, ds,   o);
            li   += __shfl_xor_sync(~0u, li,   o);
        }

        if (lane == 0) {
            float npos = (float)__popc(mask);
            float S = psum;
            if ((mask & 0x3FFFu) == 0x3FFFu) {   // nneg == 0 edge case
                S = 0.f;
                for (int c = 0; c < NCLS; c++) S += softplus_f(-s_dot[wid][c]);
            }
            float base = S / npos;
            float tv = (npos > 1.5f) ? (ds - gs / npos) / (npos - 1.f) : 0.f;
            float loss = 2.f * (0.7f * (1.f + tv) * base + 0.3f * (0.5f * li));
            wacc += loss;
        }
    }

    // --- block-local then grid reduction (deterministic fixed-order sums) ---
    if (lane == 0) s_wsum[wid] = wacc;
    __syncthreads();
    if (tid == 0) {
        float b = 0.f;
        #pragma unroll
        for (int i = 0; i < WPB; i++) b += s_wsum[i];
        g_block[blockIdx.x] = b;
        __threadfence();
        unsigned t = atomicAdd(&g_count, 1);
        s_last = (t == GRID - 1);
    }
    __syncthreads();
    if (s_last && wid == 0) {
        __threadfence();
        float t = 0.f;
        for (int i = lane; i < GRID; i += 32) {
            float bv; asm volatile("ld.global.cg.f32 %0, [%1];" : "=f"(bv) : "l"(g_block + i));
            t += bv;
        }
        #pragma unroll
        for (int o = 16; o; o >>= 1) t += __shfl_xor_sync(~0u, t, o);
        if (lane == 0) {
            out[0] = t * (1.0f / (float)BATCH);
            g_count = 0;                        // reset for next replay
        }
    }
}

extern "C" void kernel_launch(void* const* d_in, const int* in_sizes, int n_in,
                              void* d_out, int out_size) {
    const float* x = nullptr; const int* y = nullptr; const float* w = nullptr;
    for (int i = 0; i < n_in; i++) {
        if      (in_sizes[i] == BATCH * ROW)   x = (const float*)d_in[i];
        else if (in_sizes[i] == BATCH * NCLS)  y = (const int*)d_in[i];
        else if (in_sizes[i] == E_LEN * NCLS)  w = (const float*)d_in[i];
    }
    main_kernel<<<GRID, TPB>>>(x, y, w, (float*)d_out);
}